// round 17
// baseline (speedup 1.0000x reference)
#include <cuda_runtime.h>
#include <cuda_fp16.h>
#include <cstdint>

#define N_NODES 50000
#define IN_F    64
#define HIDDEN  512
#define N_EDGES 160000
#define N_TRAIN 80000
#define N_CLASS 7
#define BN_EPS  1e-5f

// ---------------- static device scratch (no allocation) ----------------
__device__ __align__(16) __half g_hA[(size_t)N_NODES * HIDDEN];
__device__ __align__(16) __half g_hB[(size_t)N_NODES * HIDDEN];
__device__ __align__(16) __half g_hC[(size_t)N_NODES * HIDDEN];
__device__ __align__(16) __half g_hX[(size_t)N_NODES * IN_F];
#define WSLOT (HIDDEN * HIDDEN)
__device__ __align__(16) __half g_wh[6 * WSLOT];

// ---------------- PTX helpers (base-target only: sm_80/90-class) ----------------
__device__ __forceinline__ uint32_t cvta_shared(const void* p) {
    uint32_t a;
    asm("{ .reg .u64 t; cvta.to.shared.u64 t, %1; cvt.u32.u64 %0, t; }" : "=r"(a) : "l"(p));
    return a;
}
#define CP16(dst, src) \
    asm volatile("cp.async.cg.shared.global [%0], [%1], 16;" :: "r"(dst), "l"(src))
#define CP_COMMIT() asm volatile("cp.async.commit_group;" ::: "memory")
#define CP_WAIT1()  asm volatile("cp.async.wait_group 1;" ::: "memory")

__device__ __forceinline__ void ldm4(uint32_t* r, uint32_t addr) {
    asm volatile("ldmatrix.sync.aligned.m8n8.x4.shared.b16 {%0,%1,%2,%3}, [%4];"
        : "=r"(r[0]), "=r"(r[1]), "=r"(r[2]), "=r"(r[3]) : "r"(addr));
}
__device__ __forceinline__ void mma16816(float* d, const uint32_t* a, const uint32_t* b) {
    asm volatile(
        "mma.sync.aligned.m16n8k16.row.col.f32.f16.f16.f32 "
        "{%0,%1,%2,%3},{%4,%5,%6,%7},{%8,%9},{%0,%1,%2,%3};"
        : "+f"(d[0]), "+f"(d[1]), "+f"(d[2]), "+f"(d[3])
        : "r"(a[0]), "r"(a[1]), "r"(a[2]), "r"(a[3]), "r"(b[0]), "r"(b[1]));
}
// fp16x2 vector reduction: 8 halves per instruction (PTX ISA 8.1)
__device__ __forceinline__ void red_add_v4h2(__half* addr, uint4 v) {
    asm volatile("red.global.add.noftz.v4.f16x2 [%0], {%1, %2, %3, %4};"
        :: "l"(addr), "r"(v.x), "r"(v.y), "r"(v.z), "r"(v.w) : "memory");
}
__device__ __forceinline__ uint32_t pack_h2(float a, float b) {
    __half2 h = __floats2half2_rn(a, b);
    return *(uint32_t*)&h;
}

// ---------------- HMMA fp16 GEMM ----------------
// C[M,512] = A[M,K] @ W[512,K]^T, both fp16.
// CTA 128x128, BK templated (64 for K=512, 32 for K=64), 3-stage cp.async,
// 2 CTAs/SM. DUAL: also emit Ch2 = (1+eps)*h (fp16) as the aggregation base.
#define GBM   128
#define GBN   128
#define NSTAGE 3
#define SMEMSZ (NSTAGE * 2 * 128 * 128)      // worst case (BK=64): 98304 -> 2 CTAs/SM

template <int BKT, bool RELU, bool BN_EN, bool DUAL>
__global__ void __launch_bounds__(256, 2)
hmma_gemm_kernel(const __half* __restrict__ A,
                 const __half* __restrict__ Bw,
                 const float* __restrict__ bias,
                 const float* __restrict__ bng, const float* __restrict__ bnb,
                 const float* __restrict__ bnm, const float* __restrict__ bnv,
                 const float* __restrict__ epsp,
                 __half* __restrict__ Ch, __half* __restrict__ Ch2,
                 int M, int K) {
    constexpr int ROWB   = BKT * 2;          // bytes per row: 128 or 64
    constexpr int CHUNKS = ROWB / 16;        // 8 or 4
    constexpr int MATB   = 128 * ROWB;
    constexpr int STB    = 2 * MATB;
    constexpr int KS     = BKT / 16;         // 4 or 2

    // swizzle: conflict-free for ldmatrix (8 consecutive rows -> 8 distinct
    // 16B bank groups at any fixed logical chunk)
    auto swz = [](uint32_t row, uint32_t c) -> uint32_t {
        if (BKT == 64)
            return row * 128u + ((c ^ (row & 7u)) << 4);
        else
            return row * 64u + ((c ^ ((row >> 1) & 3u)) << 4);
    };

    extern __shared__ char smem[];
    const uint32_t sb = cvta_shared(smem);
    const int tid = threadIdx.x, lane = tid & 31, wid = tid >> 5;
    const int wm = wid >> 1, wn = wid & 1;           // 4x2 warp grid
    const int rowBase = blockIdx.y * GBM;
    const int colBase = blockIdx.x * GBN;
    const int NC = K / BKT;

    float acc[2][8][4];
#pragma unroll
    for (int a = 0; a < 2; a++)
#pragma unroll
        for (int b = 0; b < 8; b++)
#pragma unroll
            for (int c = 0; c < 4; c++) acc[a][b][c] = 0.0f;

    auto load_stage = [&](int c) {
        const int st = c % NSTAGE;
        const uint32_t base = sb + st * STB;
        const int kOff = c * BKT;
#pragma unroll
        for (int u = 0; u < (128 * CHUNKS) / 256; u++) {
            int idx = tid + u * 256;
            uint32_t row = (uint32_t)idx / CHUNKS, ch = (uint32_t)idx % CHUNKS;
            int gr = rowBase + (int)row;
            if (gr > M - 1) gr = M - 1;       // clamp (finite junk, rows not stored)
            uint32_t so = swz(row, ch);
            CP16(base + so, A + (size_t)gr * K + kOff + ch * 8);
            CP16(base + MATB + so, Bw + (size_t)(colBase + (int)row) * K + kOff + ch * 8);
        }
        CP_COMMIT();
    };

    // ldmatrix per-lane row indices (chunk varies with ks -> swizzled per use)
    const uint32_t mrow = (uint32_t)((lane & 7) + ((lane >> 3) & 1) * 8);
    const uint32_t aChunkBit = (uint32_t)(lane >> 4);          // 0/1
    const uint32_t nrow = (uint32_t)((lane & 7) + ((lane >> 4) << 3));
    const uint32_t bChunkBit = (uint32_t)((lane >> 3) & 1);    // 0/1

    load_stage(0);
    if (NC > 1) load_stage(1); else CP_COMMIT();

    for (int c = 0; c < NC; c++) {
        CP_WAIT1();                           // own copies for stage c done
        __syncthreads();                      // publish ALL threads' stage-c data
        if (c + 2 < NC) load_stage(c + 2);    // overwrites stage (c-1)%3 (safe: sync above)
        else            CP_COMMIT();          // keep group count uniform

        const int st = c % NSTAGE;
        const uint32_t aB = sb + st * STB;
        const uint32_t bB = aB + MATB;
#pragma unroll
        for (int ks = 0; ks < KS; ks++) {
            const uint32_t cA = (uint32_t)ks * 2 + aChunkBit;
            const uint32_t cB = (uint32_t)ks * 2 + bChunkBit;
            uint32_t af[2][4], bf[4][4];
#pragma unroll
            for (int mt = 0; mt < 2; mt++)
                ldm4(af[mt], aB + swz((uint32_t)(wm * 32 + mt * 16) + mrow, cA));
#pragma unroll
            for (int jp = 0; jp < 4; jp++)
                ldm4(bf[jp], bB + swz((uint32_t)(wn * 64 + jp * 16) + nrow, cB));
#pragma unroll
            for (int mt = 0; mt < 2; mt++)
#pragma unroll
                for (int j = 0; j < 8; j++)
                    mma16816(acc[mt][j], af[mt], &bf[j >> 1][(j & 1) * 2]);
        }
        // no trailing sync: 3 distinct stage buffers; next iteration's top
        // sync orders all compute before buffer reuse.
    }

    // ---------------- epilogue (direct from registers) ----------------
    const int g = lane >> 2, t = lane & 3;
    const float es = DUAL ? (1.0f + *epsp) : 0.0f;
#pragma unroll
    for (int mt = 0; mt < 2; mt++) {
        int rbase = rowBase + wm * 32 + mt * 16 + g;
#pragma unroll
        for (int half = 0; half < 2; half++) {
            int r = rbase + half * 8;
            if (r >= M) continue;
#pragma unroll
            for (int j = 0; j < 8; j++) {
                int cidx = colBase + wn * 64 + j * 8 + 2 * t;
                float v0 = acc[mt][j][half * 2 + 0] + bias[cidx];
                float v1 = acc[mt][j][half * 2 + 1] + bias[cidx + 1];
                if (RELU) { v0 = fmaxf(v0, 0.0f); v1 = fmaxf(v1, 0.0f); }
                if (BN_EN) {
                    v0 = (v0 - bnm[cidx]) * rsqrtf(bnv[cidx] + BN_EPS) * bng[cidx] + bnb[cidx];
                    v1 = (v1 - bnm[cidx + 1]) * rsqrtf(bnv[cidx + 1] + BN_EPS) * bng[cidx + 1] + bnb[cidx + 1];
                }
                *(uint32_t*)(Ch + (size_t)r * HIDDEN + cidx) = pack_h2(v0, v1);
                if (DUAL)
                    *(uint32_t*)(Ch2 + (size_t)r * HIDDEN + cidx) =
                        pack_h2(v0 * es, v1 * es);
            }
        }
    }
}

// ---------------- auxiliary kernels ----------------
// x (fp32) -> hX = fp16(x), hA = fp16((1+eps1)*x). One pass.
__global__ void quantx_kernel(const float4* __restrict__ x, uint32_t* __restrict__ hX,
                              uint32_t* __restrict__ hA, const float* __restrict__ eps,
                              int n4) {
    float s = 1.0f + *eps;
    int i = blockIdx.x * blockDim.x + threadIdx.x;
    if (i >= n4) return;
    float4 v = x[i];
    hX[2 * i]     = pack_h2(v.x, v.y);
    hX[2 * i + 1] = pack_h2(v.z, v.w);
    hA[2 * i]     = pack_h2(v.x * s, v.y * s);
    hA[2 * i + 1] = pack_h2(v.z * s, v.w * s);
}

// fp16 scatter for F=64: 4 edges per warp (8 lanes each, 1 uint4 per lane)
__global__ void scatter64_f16_kernel(const __half* __restrict__ h, __half* __restrict__ out,
                                     const int* __restrict__ src, const int* __restrict__ dst,
                                     int nEdges) {
    int t = blockIdx.x * blockDim.x + threadIdx.x;
    int e = t >> 3, c = t & 7;
    if (e >= nEdges) return;
    int s = src[e], d = dst[e];
    uint4 v = *(const uint4*)(h + (size_t)s * IN_F + c * 8);
    red_add_v4h2(out + (size_t)d * IN_F + c * 8, v);
}

// fp16 scatter for F=512: one warp per edge, 64 uint4 per row
__global__ void scatter_add_f16_kernel(const __half* __restrict__ h, __half* __restrict__ out,
                                       const int* __restrict__ src, const int* __restrict__ dst,
                                       int nEdges) {
    int warp = (blockIdx.x * blockDim.x + threadIdx.x) >> 5;
    int lane = threadIdx.x & 31;
    if (warp >= nEdges) return;
    int s = src[warp], d = dst[warp];
    const uint4* hs = (const uint4*)(h + (size_t)s * HIDDEN);
    __half* od = out + (size_t)d * HIDDEN;
#pragma unroll
    for (int i = lane; i < HIDDEN / 8; i += 32) {
        uint4 v = hs[i];
        red_add_v4h2(od + 8 * i, v);
    }
}

// All 6 weights: W[K,N] f32 -> Wt[N,K] fp16 (transpose + cast). z = weight idx.
__global__ void wsplit_all_kernel(const float* __restrict__ W0, const float* __restrict__ W1p,
                                  const float* __restrict__ W2p, const float* __restrict__ W3p,
                                  const float* __restrict__ W4p, const float* __restrict__ W5p,
                                  __half* __restrict__ Wh) {
    __shared__ float t[32][33];
    int z = blockIdx.z;
    const float* W = z == 0 ? W0 : z == 1 ? W1p : z == 2 ? W2p : z == 3 ? W3p
                   : z == 4 ? W4p : W5p;
    int K = (z == 0) ? IN_F : HIDDEN;
    int k0 = blockIdx.y * 32;
    if (k0 >= K) return;
    int n0 = blockIdx.x * 32;
    int tx = threadIdx.x, ty = threadIdx.y;
#pragma unroll
    for (int i = 0; i < 4; i++)
        t[ty + i * 8][tx] = W[(size_t)(k0 + ty + i * 8) * HIDDEN + n0 + tx];
    __syncthreads();
    __half* dst = Wh + (size_t)z * WSLOT;
#pragma unroll
    for (int i = 0; i < 4; i++) {
        float v = t[tx][ty + i * 8];
        dst[(size_t)(n0 + ty + i * 8) * K + k0 + tx] = __float2half_rn(v);
    }
}

// edge classifier reading fp16 h: out[t,:] = (h[n0]*h[n1]) @ fc2_W + fc2_b
// smem weights fp16, [N_CLASS][HIDDEN]; 512 threads/block to amortize load.
__global__ void __launch_bounds__(512)
edge_pred_kernel(const __half* __restrict__ h, const int* __restrict__ ei,
                 const int* __restrict__ train_id, const float* __restrict__ W,
                 const float* __restrict__ b, float* __restrict__ out) {
    __shared__ __half sWT[N_CLASS * HIDDEN];  // [j][k]
    __shared__ float sb[N_CLASS];
    for (int i = threadIdx.x; i < N_CLASS * HIDDEN; i += blockDim.x) {
        int j = i >> 9, k = i & 511;          // i = j*512 + k
        sWT[i] = __float2half_rn(W[k * N_CLASS + j]);
    }
    if (threadIdx.x < N_CLASS) sb[threadIdx.x] = b[threadIdx.x];
    __syncthreads();
    int warp = (blockIdx.x * blockDim.x + threadIdx.x) >> 5;
    int lane = threadIdx.x & 31;
    if (warp >= N_TRAIN) return;
    int te = train_id[warp];
    int n0 = ei[te], n1 = ei[N_EDGES + te];
    const uint4* h0 = (const uint4*)(h + (size_t)n0 * HIDDEN);
    const uint4* h1 = (const uint4*)(h + (size_t)n1 * HIDDEN);
    float acc[N_CLASS];
#pragma unroll
    for (int j = 0; j < N_CLASS; j++) acc[j] = 0.0f;
    for (int i = lane; i < HIDDEN / 8; i += 32) {   // 8 halves per uint4
        uint4 a4 = h0[i], c4 = h1[i];
        const __half2* ah = (const __half2*)&a4;
        const __half2* ch = (const __half2*)&c4;
        float p[8];
#pragma unroll
        for (int q = 0; q < 4; q++) {
            float2 af = __half22float2(ah[q]);
            float2 cf = __half22float2(ch[q]);
            p[2 * q]     = af.x * cf.x;
            p[2 * q + 1] = af.y * cf.y;
        }
#pragma unroll
        for (int j = 0; j < N_CLASS; j++) {
            uint4 w4 = *(const uint4*)(sWT + j * HIDDEN + i * 8);
            const __half2* wh2 = (const __half2*)&w4;
#pragma unroll
            for (int q = 0; q < 4; q++) {
                float2 wf = __half22float2(wh2[q]);
                acc[j] += p[2 * q] * wf.x + p[2 * q + 1] * wf.y;
            }
        }
    }
#pragma unroll
    for (int j = 0; j < N_CLASS; j++)
#pragma unroll
        for (int off = 16; off > 0; off >>= 1)
            acc[j] += __shfl_xor_sync(0xffffffffu, acc[j], off);
    if (lane == 0) {
#pragma unroll
        for (int j = 0; j < N_CLASS; j++)
            out[(size_t)warp * N_CLASS + j] = acc[j] + sb[j];
    }
}

// ---------------- launcher ----------------
extern "C" void kernel_launch(void* const* d_in, const int* in_sizes, int n_in,
                              void* d_out, int out_size) {
    const float* x     = (const float*)d_in[0];
    const int*   ei    = (const int*)d_in[1];
    const int*   trid  = (const int*)d_in[2];
    const float* W1    = (const float*)d_in[3];
    const float* b1    = (const float*)d_in[4];
    const float* W2    = (const float*)d_in[5];
    const float* b2    = (const float*)d_in[6];
    const float* W3    = (const float*)d_in[7];
    const float* b3    = (const float*)d_in[8];
    const float* bn1g  = (const float*)d_in[9];
    const float* bn1b  = (const float*)d_in[10];
    const float* bn1m  = (const float*)d_in[11];
    const float* bn1v  = (const float*)d_in[12];
    const float* eps1  = (const float*)d_in[13];
    const float* W4    = (const float*)d_in[14];
    const float* b4    = (const float*)d_in[15];
    const float* bn2g  = (const float*)d_in[16];
    const float* bn2b  = (const float*)d_in[17];
    const float* bn2m  = (const float*)d_in[18];
    const float* bn2v  = (const float*)d_in[19];
    const float* eps2  = (const float*)d_in[20];
    const float* lin1W = (const float*)d_in[21];
    const float* lin1b = (const float*)d_in[22];
    const float* lin2W = (const float*)d_in[23];
    const float* lin2b = (const float*)d_in[24];
    const float* fc2W  = (const float*)d_in[25];
    const float* fc2b  = (const float*)d_in[26];
    float* out = (float*)d_out;

    __half *hA, *hB, *hC, *hX, *wh;
    cudaGetSymbolAddress((void**)&hA, g_hA);
    cudaGetSymbolAddress((void**)&hB, g_hB);
    cudaGetSymbolAddress((void**)&hC, g_hC);
    cudaGetSymbolAddress((void**)&hX, g_hX);
    cudaGetSymbolAddress((void**)&wh, g_wh);

    cudaFuncSetAttribute(hmma_gemm_kernel<32, true, false, false>,
                         cudaFuncAttributeMaxDynamicSharedMemorySize, SMEMSZ);
    cudaFuncSetAttribute(hmma_gemm_kernel<64, true, false, false>,
                         cudaFuncAttributeMaxDynamicSharedMemorySize, SMEMSZ);
    cudaFuncSetAttribute(hmma_gemm_kernel<64, true, true, true>,
                         cudaFuncAttributeMaxDynamicSharedMemorySize, SMEMSZ);
    cudaFuncSetAttribute(hmma_gemm_kernel<64, true, true, false>,
                         cudaFuncAttributeMaxDynamicSharedMemorySize, SMEMSZ);
    cudaFuncSetAttribute(hmma_gemm_kernel<64, false, false, false>,
                         cudaFuncAttributeMaxDynamicSharedMemorySize, SMEMSZ);

    const int* src = ei;
    const int* dst = ei + N_EDGES;

    // all weight transposes + fp16 casts in one launch
    wsplit_all_kernel<<<dim3(16, 16, 6), dim3(32, 8)>>>(W1, W2, W3, W4, lin1W, lin2W, wh);

    // agg1 fully fp16: hX = fp16(x), hA = fp16((1+eps1)x); hA[dst] += hX[src]
    {
        int n4 = N_NODES * IN_F / 4;
        quantx_kernel<<<(n4 + 255) / 256, 256>>>((const float4*)x, (uint32_t*)hX,
                                                 (uint32_t*)hA, eps1, n4);
        scatter64_f16_kernel<<<(N_EDGES * 8 + 255) / 256, 256>>>(hX, hA, src, dst, N_EDGES);
    }

    dim3 gg(HIDDEN / GBN, (N_NODES + GBM - 1) / GBM);  // (4, 391)

    // L1: relu(agg @ W1 + b1) -> hB  (K=64: BK=32 pipelined variant)
    hmma_gemm_kernel<32, true, false, false><<<gg, 256, SMEMSZ>>>(
        hA, wh + 0 * WSLOT, b1, nullptr, nullptr, nullptr, nullptr,
        nullptr, hB, nullptr, N_NODES, IN_F);
    // L2: relu(h @ W2 + b2) -> hA
    hmma_gemm_kernel<64, true, false, false><<<gg, 256, SMEMSZ>>>(
        hB, wh + 1 * WSLOT, b2, nullptr, nullptr, nullptr, nullptr,
        nullptr, hA, nullptr, N_NODES, HIDDEN);
    // L3: bn1(relu(h @ W3 + b3)) -> hB (h) + hC ((1+eps2)*h, fused agg base)
    hmma_gemm_kernel<64, true, true, true><<<gg, 256, SMEMSZ>>>(
        hA, wh + 2 * WSLOT, b3, bn1g, bn1b, bn1m, bn1v,
        eps2, hB, hC, N_NODES, HIDDEN);
    // agg2 (fp16): hC[dst] += hB[src]
    scatter_add_f16_kernel<<<(N_EDGES * 32 + 255) / 256, 256>>>(hB, hC, src, dst, N_EDGES);
    // L4: bn2(relu(h @ W4 + b4)) -> hA
    hmma_gemm_kernel<64, true, true, false><<<gg, 256, SMEMSZ>>>(
        hC, wh + 3 * WSLOT, b4, bn2g, bn2b, bn2m, bn2v,
        nullptr, hA, nullptr, N_NODES, HIDDEN);
    // L5: relu(h @ lin1W + lin1b) -> hB
    hmma_gemm_kernel<64, true, false, false><<<gg, 256, SMEMSZ>>>(
        hA, wh + 4 * WSLOT, lin1b, nullptr, nullptr, nullptr, nullptr,
        nullptr, hB, nullptr, N_NODES, HIDDEN);
    // L6: h @ lin2W + lin2b -> hC
    hmma_gemm_kernel<64, false, false, false><<<gg, 256, SMEMSZ>>>(
        hB, wh + 5 * WSLOT, lin2b, nullptr, nullptr, nullptr, nullptr,
        nullptr, hC, nullptr, N_NODES, HIDDEN);
    // edge classifier (fp16 h)
    edge_pred_kernel<<<(N_TRAIN * 32 + 511) / 512, 512>>>(hC, ei, trid, fc2W, fc2b, out);
}